// round 3
// baseline (speedup 1.0000x reference)
#include <cuda_runtime.h>
#include <cstdint>

#define N_NODES 50000
#define N_EDGES 800000
#define CNT_BLOCKS 782          // matches gemm grid.x so count rides in grid z=0
#define SCAN_BLOCKS ((N_NODES + 255) / 256)   // 196

// ---------------- scratch (static __device__, zero-initialized at load) ----------------
__device__ float g_Q[N_NODES * 128];
__device__ float g_K[N_NODES * 128];
__device__ float g_V[N_NODES * 128];
__device__ int   g_row_off[N_NODES + 1];
__device__ int   g_cnt[N_NODES];      // counts -> cursors; re-zeroed by aggregate
__device__ int   g_esrc[N_EDGES];     // src node id per CSR slot
__device__ int   g_part[SCAN_BLOCKS];

// packed f32x2 helpers (sm_103a FFMA2 path — only reachable via explicit PTX)
__device__ __forceinline__ uint64_t dup_f32x2(float a) {
    uint64_t r;
    asm("mov.b64 %0, {%1, %1};" : "=l"(r) : "f"(a));
    return r;
}
__device__ __forceinline__ void fma_f32x2(uint64_t& acc, uint64_t a, uint64_t b) {
    asm("fma.rn.f32x2 %0, %1, %2, %0;" : "+l"(acc) : "l"(a), "l"(b));
}
__device__ __forceinline__ void unpack_f32x2(uint64_t v, float& lo, float& hi) {
    asm("mov.b64 {%0, %1}, %2;" : "=f"(lo), "=f"(hi) : "l"(v));
}

// ---------------- fused QKV GEMM + edge count ----------------
// grid = (782, 1, 4): z==0 -> degree count (hidden under GEMM wave 1)
//                     z in {1,2,3} -> C[z-1] = h @ W + b, BM=64,BN=128,BK=16.
// Inner microtile uses packed fma.rn.f32x2: 16 FFMA2 per k instead of 32 FFMA.
__global__ void __launch_bounds__(256) gemm_qkv_count(
    const float* __restrict__ h, const int* __restrict__ dst,
    const float* __restrict__ Wq, const float* __restrict__ bq,
    const float* __restrict__ Wk, const float* __restrict__ bk,
    const float* __restrict__ Wv, const float* __restrict__ bv)
{
    const int z = blockIdx.z;
    if (z == 0) {
        int tid = blockIdx.x * 256 + threadIdx.x;
        for (int e = tid; e < N_EDGES; e += CNT_BLOCKS * 256)
            atomicAdd(&g_cnt[dst[e]], 1);
        return;
    }

    const float* W; const float* bias; float* C;
    if (z == 1)      { W = Wq; bias = bq; C = g_Q; }
    else if (z == 2) { W = Wk; bias = bk; C = g_K; }
    else             { W = Wv; bias = bv; C = g_V; }

    __shared__ float As[16][64];    // [k][m]
    __shared__ float Bs[16][128];   // [k][n]

    const int t    = threadIdx.x;
    const int row0 = blockIdx.x * 64;
    const int tidx = t & 15;        // col group (8 cols each = 4 packed pairs)
    const int tidy = t >> 4;        // row group (4 rows each)

    uint64_t acc2[4][4];            // [i][jp] : packed pair of output cols
    #pragma unroll
    for (int i = 0; i < 4; i++)
        #pragma unroll
        for (int j = 0; j < 4; j++) acc2[i][j] = 0ull;

    const int a_row = t >> 2;         // 0..63
    const int a_k   = (t & 3) * 4;    // 0,4,8,12
    const int b_row = t >> 5;         // 0..7
    const int b_col = (t & 31) * 4;   // 0..124

    for (int k0 = 0; k0 < 128; k0 += 16) {
        float4 av = make_float4(0.f, 0.f, 0.f, 0.f);
        int gr = row0 + a_row;
        if (gr < N_NODES)
            av = *reinterpret_cast<const float4*>(&h[gr * 128 + k0 + a_k]);
        As[a_k + 0][a_row] = av.x;
        As[a_k + 1][a_row] = av.y;
        As[a_k + 2][a_row] = av.z;
        As[a_k + 3][a_row] = av.w;

        float4 bv0 = *reinterpret_cast<const float4*>(&W[(k0 + b_row) * 128 + b_col]);
        float4 bv1 = *reinterpret_cast<const float4*>(&W[(k0 + 8 + b_row) * 128 + b_col]);
        *reinterpret_cast<float4*>(&Bs[b_row][b_col])     = bv0;
        *reinterpret_cast<float4*>(&Bs[b_row + 8][b_col]) = bv1;
        __syncthreads();

        #pragma unroll
        for (int k = 0; k < 16; k++) {
            float4 a4 = *reinterpret_cast<const float4*>(&As[k][tidy * 4]);
            const uint64_t* bp = reinterpret_cast<const uint64_t*>(&Bs[k][tidx * 8]);
            uint64_t b2[4];
            #pragma unroll
            for (int j = 0; j < 4; j++) b2[j] = bp[j];
            uint64_t a2[4];
            a2[0] = dup_f32x2(a4.x);
            a2[1] = dup_f32x2(a4.y);
            a2[2] = dup_f32x2(a4.z);
            a2[3] = dup_f32x2(a4.w);
            #pragma unroll
            for (int i = 0; i < 4; i++)
                #pragma unroll
                for (int j = 0; j < 4; j++)
                    fma_f32x2(acc2[i][j], a2[i], b2[j]);
        }
        __syncthreads();
    }

    #pragma unroll
    for (int i = 0; i < 4; i++) {
        int gr = row0 + tidy * 4 + i;
        if (gr >= N_NODES) continue;
        float r[8];
        #pragma unroll
        for (int j = 0; j < 4; j++) unpack_f32x2(acc2[i][j], r[2 * j], r[2 * j + 1]);
        #pragma unroll
        for (int j = 0; j < 8; j += 4) {
            int col = tidx * 8 + j;
            float4 o;
            o.x = r[j + 0] + bias[col + 0];
            o.y = r[j + 1] + bias[col + 1];
            o.z = r[j + 2] + bias[col + 2];
            o.w = r[j + 3] + bias[col + 3];
            *reinterpret_cast<float4*>(&C[gr * 128 + col]) = o;
        }
    }
}

// ---------------- parallel scan, stage 1: per-block (256-wide) sums ----------------
__global__ void __launch_bounds__(256) scan_part_kernel()
{
    __shared__ int ws[8];
    int gid = blockIdx.x * 256 + threadIdx.x;
    int v = (gid < N_NODES) ? g_cnt[gid] : 0;
    int s = __reduce_add_sync(0xffffffffu, v);
    if ((threadIdx.x & 31) == 0) ws[threadIdx.x >> 5] = s;
    __syncthreads();
    if (threadIdx.x == 0) {
        int tot = 0;
        #pragma unroll
        for (int j = 0; j < 8; j++) tot += ws[j];
        g_part[blockIdx.x] = tot;
    }
}

// ---------------- parallel scan, stage 2: block offset + intra-block exclusive scan ----------------
__global__ void __launch_bounds__(256) scan_final_kernel()
{
    __shared__ int ps[8];
    __shared__ int ws[8];
    const int t = threadIdx.x, b = blockIdx.x;
    const int lane = t & 31, w = t >> 5;

    int pv = (t < b) ? g_part[t] : 0;
    int psum = __reduce_add_sync(0xffffffffu, pv);
    if (lane == 0) ps[w] = psum;
    __syncthreads();
    int offset = 0;
    #pragma unroll
    for (int j = 0; j < 8; j++) offset += ps[j];

    int gid = b * 256 + t;
    int c = (gid < N_NODES) ? g_cnt[gid] : 0;
    int incl = c;
    #pragma unroll
    for (int d = 1; d < 32; d <<= 1) {
        int u = __shfl_up_sync(0xffffffffu, incl, d);
        if (lane >= d) incl += u;
    }
    if (lane == 31) ws[w] = incl;
    __syncthreads();
    int woff = 0;
    #pragma unroll
    for (int j = 0; j < 8; j++) woff += (j < w) ? ws[j] : 0;

    int excl = offset + woff + incl - c;
    if (gid < N_NODES) {
        g_row_off[gid] = excl;
        g_cnt[gid]     = excl;           // cursor for scatter
    }
    if (gid == N_NODES - 1)
        g_row_off[N_NODES] = excl + c;
}

// ---------------- scatter: bucket src ids by dst ----------------
__global__ void __launch_bounds__(256) scatter_kernel(
    const int* __restrict__ src, const int* __restrict__ dst)
{
    int e = blockIdx.x * blockDim.x + threadIdx.x;
    if (e < N_EDGES) {
        int p = atomicAdd(&g_cnt[dst[e]], 1);
        g_esrc[p] = src[e];
    }
}

// ---------------- aggregation: one warp per dst node ----------------
// lane l owns columns 4l..4l+3; each 4-lane quad owns one head (D=16).
// Restores g_cnt[node]=0 so the counter invariant holds for the next replay.
__global__ void __launch_bounds__(256) aggregate_kernel(float* __restrict__ out)
{
    int warp = (blockIdx.x * blockDim.x + threadIdx.x) >> 5;
    int lane = threadIdx.x & 31;
    if (warp >= N_NODES) return;
    const int node = warp;

    const float4 q = *reinterpret_cast<const float4*>(&g_Q[node * 128 + lane * 4]);
    float4 acc = make_float4(0.f, 0.f, 0.f, 0.f);
    float  zz  = 0.f;

    const int beg = g_row_off[node];
    const int end = g_row_off[node + 1];
    for (int i = beg; i < end; ++i) {
        int s = g_esrc[i];
        const float4 k4 = *reinterpret_cast<const float4*>(&g_K[s * 128 + lane * 4]);
        float p = q.x * k4.x + q.y * k4.y + q.z * k4.z + q.w * k4.w;
        p += __shfl_xor_sync(0xffffffffu, p, 1);
        p += __shfl_xor_sync(0xffffffffu, p, 2);
        float sc = p * 0.25f;                       // 1/sqrt(16)
        sc = fminf(fmaxf(sc, -5.f), 5.f);
        float wgt = __expf(sc);
        const float4 v4 = *reinterpret_cast<const float4*>(&g_V[s * 128 + lane * 4]);
        acc.x += v4.x * wgt;
        acc.y += v4.y * wgt;
        acc.z += v4.z * wgt;
        acc.w += v4.w * wgt;
        zz += wgt;                                  // same across quad = z[head]
    }

    float inv = 1.f / (zz + 1e-6f);
    float4 o = make_float4(acc.x * inv, acc.y * inv, acc.z * inv, acc.w * inv);
    *reinterpret_cast<float4*>(&out[node * 128 + lane * 4]) = o;

    if (lane == 0) g_cnt[node] = 0;                 // restore invariant for next launch
}

// ---------------- launch ----------------
extern "C" void kernel_launch(void* const* d_in, const int* in_sizes, int n_in,
                              void* d_out, int out_size)
{
    const float* h   = (const float*)d_in[0];
    // d_in[1] (e), d_in[8] (We), d_in[9] (be) are unused by the reference output.
    const int*   src = (const int*)d_in[2];
    const int*   dst = (const int*)d_in[3];
    const float* Wq  = (const float*)d_in[4];
    const float* bq  = (const float*)d_in[5];
    const float* Wk  = (const float*)d_in[6];
    const float* bk  = (const float*)d_in[7];
    const float* Wv  = (const float*)d_in[10];
    const float* bv  = (const float*)d_in[11];
    float* out = (float*)d_out;

    dim3 grid(CNT_BLOCKS, 1, 4);   // z=0: count, z=1..3: Q,K,V GEMM tiles
    gemm_qkv_count<<<grid, 256>>>(h, dst, Wq, bq, Wk, bk, Wv, bv);

    scan_part_kernel<<<SCAN_BLOCKS, 256>>>();
    scan_final_kernel<<<SCAN_BLOCKS, 256>>>();
    scatter_kernel<<<(N_EDGES + 255) / 256, 256>>>(src, dst);

    int agg_blocks = (N_NODES + 7) / 8;   // 8 warps (nodes) per 256-thread block
    aggregate_kernel<<<agg_blocks, 256>>>(out);
}

// round 4
// speedup vs baseline: 1.6329x; 1.6329x over previous
#include <cuda_runtime.h>
#include <cuda_bf16.h>
#include <cstdint>

#define N_NODES 50000
#define N_EDGES 800000
#define SCAN_BLOCKS ((N_NODES + 255) / 256)   // 196
#define M_TILES (N_NODES / 16)                // 3125, exact

// ---------------- scratch (static __device__, zero-initialized at load) ----------------
__device__ float g_Q[N_NODES * 128];
__device__ float g_K[N_NODES * 128];
__device__ float g_V[N_NODES * 128];
__device__ int   g_row_off[N_NODES + 1];
__device__ int   g_cnt[N_NODES];              // counts -> cursors; re-zeroed by aggregate
__device__ int   g_esrc[N_EDGES];             // src node id per CSR slot
__device__ int   g_part[SCAN_BLOCKS];

// bf16 split of h, packed 4 elems per uint2 (row-major halfword order)
__device__ uint2 g_hhi[N_NODES * 128 / 4];
__device__ uint2 g_hlo[N_NODES * 128 / 4];
// pre-swizzled weight fragments: [z][kstep][ntile][lane] -> {reg0, reg1} of mma B frag
__device__ uint2 g_wfhi[3][8][16][32];
__device__ uint2 g_wflo[3][8][16][32];

__device__ __forceinline__ uint32_t pack_bf2(__nv_bfloat16 a, __nv_bfloat16 b) {
    return (uint32_t)__bfloat16_as_ushort(a) | ((uint32_t)__bfloat16_as_ushort(b) << 16);
}

// ---------------- prep: z=0 split h, z=1 edge count, z=2 weight fragments ----------------
__global__ void __launch_bounds__(256) prep_kernel(
    const float* __restrict__ h, const int* __restrict__ dst,
    const float* __restrict__ Wq, const float* __restrict__ Wk, const float* __restrict__ Wv)
{
    const int z = blockIdx.z;
    const int tid = blockIdx.x * 256 + threadIdx.x;

    if (z == 0) {
        // 6.4M floats / 4 per thread = 1.6M threads = 6250 blocks exactly
        float4 v = *reinterpret_cast<const float4*>(&h[tid * 4]);
        __nv_bfloat16 h0 = __float2bfloat16_rn(v.x);
        __nv_bfloat16 h1 = __float2bfloat16_rn(v.y);
        __nv_bfloat16 h2 = __float2bfloat16_rn(v.z);
        __nv_bfloat16 h3 = __float2bfloat16_rn(v.w);
        uint2 hi, lo;
        hi.x = pack_bf2(h0, h1);
        hi.y = pack_bf2(h2, h3);
        lo.x = pack_bf2(__float2bfloat16_rn(v.x - __bfloat162float(h0)),
                        __float2bfloat16_rn(v.y - __bfloat162float(h1)));
        lo.y = pack_bf2(__float2bfloat16_rn(v.z - __bfloat162float(h2)),
                        __float2bfloat16_rn(v.w - __bfloat162float(h3)));
        g_hhi[tid] = hi;
        g_hlo[tid] = lo;
    } else if (z == 1) {
        if (tid < N_EDGES) atomicAdd(&g_cnt[dst[tid]], 1);
    } else {
        // weight fragments: 3*8*16*32 = 12288 threads
        if (tid >= 3 * 8 * 16 * 32) return;
        int lane = tid & 31;
        int nt   = (tid >> 5) & 15;
        int ks   = (tid >> 9) & 7;
        int zz   = tid >> 12;
        const float* W = (zz == 0) ? Wq : (zz == 1) ? Wk : Wv;
        int g = lane >> 2, t = lane & 3;
        int n  = nt * 8 + g;
        int kb = ks * 16 + t * 2;
        float w0 = W[(kb + 0) * 128 + n];
        float w1 = W[(kb + 1) * 128 + n];
        float w2 = W[(kb + 8) * 128 + n];
        float w3 = W[(kb + 9) * 128 + n];
        __nv_bfloat16 b0 = __float2bfloat16_rn(w0);
        __nv_bfloat16 b1 = __float2bfloat16_rn(w1);
        __nv_bfloat16 b2 = __float2bfloat16_rn(w2);
        __nv_bfloat16 b3 = __float2bfloat16_rn(w3);
        uint2 hi, lo;
        hi.x = pack_bf2(b0, b1);
        hi.y = pack_bf2(b2, b3);
        lo.x = pack_bf2(__float2bfloat16_rn(w0 - __bfloat162float(b0)),
                        __float2bfloat16_rn(w1 - __bfloat162float(b1)));
        lo.y = pack_bf2(__float2bfloat16_rn(w2 - __bfloat162float(b2)),
                        __float2bfloat16_rn(w3 - __bfloat162float(b3)));
        g_wfhi[zz][ks][nt][lane] = hi;
        g_wflo[zz][ks][nt][lane] = lo;
    }
}

// ---------------- tensor-core GEMM: C[z] = h @ W[z] + b[z] via bf16-split ----------------
// CTA = 16 m-rows x 128 n-cols x 3 weights. 4 warps; warp w owns n-tiles [4w, 4w+4).
__device__ __forceinline__ void mma_bf16(float& c0, float& c1, float& c2, float& c3,
                                         uint32_t a0, uint32_t a1, uint32_t a2, uint32_t a3,
                                         uint32_t b0, uint32_t b1)
{
    asm volatile(
        "mma.sync.aligned.m16n8k16.row.col.f32.bf16.bf16.f32 "
        "{%0,%1,%2,%3},{%4,%5,%6,%7},{%8,%9},{%0,%1,%2,%3};"
        : "+f"(c0), "+f"(c1), "+f"(c2), "+f"(c3)
        : "r"(a0), "r"(a1), "r"(a2), "r"(a3), "r"(b0), "r"(b1));
}

__global__ void __launch_bounds__(128) gemm_mma(
    const float* __restrict__ bq, const float* __restrict__ bk, const float* __restrict__ bv)
{
    const int m0   = blockIdx.x * 16;
    const int w    = threadIdx.x >> 5;
    const int lane = threadIdx.x & 31;
    const int g    = lane >> 2;
    const int t    = lane & 3;

    float c[3][4][4];
    #pragma unroll
    for (int z = 0; z < 3; z++) {
        const float* bias = (z == 0) ? bq : (z == 1) ? bk : bv;
        #pragma unroll
        for (int nt = 0; nt < 4; nt++) {
            int col = (w * 4 + nt) * 8 + t * 2;
            float b0 = bias[col], b1 = bias[col + 1];
            c[z][nt][0] = b0; c[z][nt][1] = b1;
            c[z][nt][2] = b0; c[z][nt][3] = b1;
        }
    }

    const uint32_t* Ahi = reinterpret_cast<const uint32_t*>(g_hhi);
    const uint32_t* Alo = reinterpret_cast<const uint32_t*>(g_hlo);
    const int rowA = m0 + g;                 // 16-bf16 rows; 64 words per row

    #pragma unroll
    for (int pass = 0; pass < 3; pass++) {
        const uint32_t* A = (pass == 2) ? Alo : Ahi;
        const bool useLo = (pass == 1);
        #pragma unroll
        for (int ks = 0; ks < 8; ks++) {
            int kw = ks * 8 + t;
            uint32_t a0 = A[rowA * 64 + kw];
            uint32_t a1 = A[(rowA + 8) * 64 + kw];
            uint32_t a2 = A[rowA * 64 + kw + 4];
            uint32_t a3 = A[(rowA + 8) * 64 + kw + 4];
            #pragma unroll
            for (int z = 0; z < 3; z++) {
                #pragma unroll
                for (int nt = 0; nt < 4; nt++) {
                    uint2 b = useLo ? g_wflo[z][ks][w * 4 + nt][lane]
                                    : g_wfhi[z][ks][w * 4 + nt][lane];
                    mma_bf16(c[z][nt][0], c[z][nt][1], c[z][nt][2], c[z][nt][3],
                             a0, a1, a2, a3, b.x, b.y);
                }
            }
        }
    }

    #pragma unroll
    for (int z = 0; z < 3; z++) {
        float* C = (z == 0) ? g_Q : (z == 1) ? g_K : g_V;
        #pragma unroll
        for (int nt = 0; nt < 4; nt++) {
            int col = (w * 4 + nt) * 8 + t * 2;
            float2 lo = make_float2(c[z][nt][0], c[z][nt][1]);
            float2 hi = make_float2(c[z][nt][2], c[z][nt][3]);
            *reinterpret_cast<float2*>(&C[(m0 + g) * 128 + col])     = lo;
            *reinterpret_cast<float2*>(&C[(m0 + g + 8) * 128 + col]) = hi;
        }
    }
}

// ---------------- parallel scan, stage 1: per-block (256-wide) sums ----------------
__global__ void __launch_bounds__(256) scan_part_kernel()
{
    __shared__ int ws[8];
    int gid = blockIdx.x * 256 + threadIdx.x;
    int v = (gid < N_NODES) ? g_cnt[gid] : 0;
    int s = __reduce_add_sync(0xffffffffu, v);
    if ((threadIdx.x & 31) == 0) ws[threadIdx.x >> 5] = s;
    __syncthreads();
    if (threadIdx.x == 0) {
        int tot = 0;
        #pragma unroll
        for (int j = 0; j < 8; j++) tot += ws[j];
        g_part[blockIdx.x] = tot;
    }
}

// ---------------- parallel scan, stage 2: block offset + intra-block exclusive scan ----------------
__global__ void __launch_bounds__(256) scan_final_kernel()
{
    __shared__ int ps[8];
    __shared__ int ws[8];
    const int t = threadIdx.x, b = blockIdx.x;
    const int lane = t & 31, w = t >> 5;

    int pv = (t < b) ? g_part[t] : 0;
    int psum = __reduce_add_sync(0xffffffffu, pv);
    if (lane == 0) ps[w] = psum;
    __syncthreads();
    int offset = 0;
    #pragma unroll
    for (int j = 0; j < 8; j++) offset += ps[j];

    int gid = b * 256 + t;
    int c = (gid < N_NODES) ? g_cnt[gid] : 0;
    int incl = c;
    #pragma unroll
    for (int d = 1; d < 32; d <<= 1) {
        int u = __shfl_up_sync(0xffffffffu, incl, d);
        if (lane >= d) incl += u;
    }
    if (lane == 31) ws[w] = incl;
    __syncthreads();
    int woff = 0;
    #pragma unroll
    for (int j = 0; j < 8; j++) woff += (j < w) ? ws[j] : 0;

    int excl = offset + woff + incl - c;
    if (gid < N_NODES) {
        g_row_off[gid] = excl;
        g_cnt[gid]     = excl;           // cursor for scatter
    }
    if (gid == N_NODES - 1)
        g_row_off[N_NODES] = excl + c;
}

// ---------------- scatter: bucket src ids by dst ----------------
__global__ void __launch_bounds__(256) scatter_kernel(
    const int* __restrict__ src, const int* __restrict__ dst)
{
    int e = blockIdx.x * blockDim.x + threadIdx.x;
    if (e < N_EDGES) {
        int p = atomicAdd(&g_cnt[dst[e]], 1);
        g_esrc[p] = src[e];
    }
}

// ---------------- aggregation: one warp per dst node ----------------
__global__ void __launch_bounds__(256) aggregate_kernel(float* __restrict__ out)
{
    int warp = (blockIdx.x * blockDim.x + threadIdx.x) >> 5;
    int lane = threadIdx.x & 31;
    if (warp >= N_NODES) return;
    const int node = warp;

    const float4 q = *reinterpret_cast<const float4*>(&g_Q[node * 128 + lane * 4]);
    float4 acc = make_float4(0.f, 0.f, 0.f, 0.f);
    float  zz  = 0.f;

    const int beg = g_row_off[node];
    const int end = g_row_off[node + 1];
    for (int i = beg; i < end; ++i) {
        int s = g_esrc[i];
        const float4 k4 = *reinterpret_cast<const float4*>(&g_K[s * 128 + lane * 4]);
        float p = q.x * k4.x + q.y * k4.y + q.z * k4.z + q.w * k4.w;
        p += __shfl_xor_sync(0xffffffffu, p, 1);
        p += __shfl_xor_sync(0xffffffffu, p, 2);
        float sc = p * 0.25f;                       // 1/sqrt(16)
        sc = fminf(fmaxf(sc, -5.f), 5.f);
        float wgt = __expf(sc);
        const float4 v4 = *reinterpret_cast<const float4*>(&g_V[s * 128 + lane * 4]);
        acc.x += v4.x * wgt;
        acc.y += v4.y * wgt;
        acc.z += v4.z * wgt;
        acc.w += v4.w * wgt;
        zz += wgt;                                  // same across quad = z[head]
    }

    float inv = 1.f / (zz + 1e-6f);
    float4 o = make_float4(acc.x * inv, acc.y * inv, acc.z * inv, acc.w * inv);
    *reinterpret_cast<float4*>(&out[node * 128 + lane * 4]) = o;

    if (lane == 0) g_cnt[node] = 0;                 // restore invariant for next launch
}

// ---------------- launch ----------------
extern "C" void kernel_launch(void* const* d_in, const int* in_sizes, int n_in,
                              void* d_out, int out_size)
{
    const float* h   = (const float*)d_in[0];
    // d_in[1] (e), d_in[8] (We), d_in[9] (be) are unused by the reference output.
    const int*   src = (const int*)d_in[2];
    const int*   dst = (const int*)d_in[3];
    const float* Wq  = (const float*)d_in[4];
    const float* bq  = (const float*)d_in[5];
    const float* Wk  = (const float*)d_in[6];
    const float* bk  = (const float*)d_in[7];
    const float* Wv  = (const float*)d_in[10];
    const float* bv  = (const float*)d_in[11];
    float* out = (float*)d_out;

    dim3 prep_grid(6250, 1, 3);    // z=0: h split (6250*256*4 = 6.4M), z=1: count, z=2: W frags
    prep_kernel<<<prep_grid, 256>>>(h, dst, Wq, Wk, Wv);

    scan_part_kernel<<<SCAN_BLOCKS, 256>>>();
    scan_final_kernel<<<SCAN_BLOCKS, 256>>>();
    scatter_kernel<<<(N_EDGES + 255) / 256, 256>>>(src, dst);

    gemm_mma<<<M_TILES, 128>>>(bq, bk, bv);

    int agg_blocks = (N_NODES + 7) / 8;   // 8 warps (nodes) per 256-thread block
    aggregate_kernel<<<agg_blocks, 256>>>(out);
}

// round 5
// speedup vs baseline: 1.7116x; 1.0482x over previous
#include <cuda_runtime.h>
#include <cuda_bf16.h>
#include <cuda_fp16.h>
#include <cstdint>

#define N_NODES 50000
#define N_EDGES 800000
#define SCAN_BLOCKS ((N_NODES + 255) / 256)   // 196
#define M_TILES (N_NODES / 16)                // 3125, exact
#define E4_BLOCKS ((N_EDGES / 4 + 255) / 256) // 782

// ---------------- scratch (static __device__, zero-initialized at load) ----------------
__device__ float    g_Q[N_NODES * 128];
__device__ uint32_t g_Kh[N_NODES * 64];       // fp16 K, half2-packed (64 half2 per row)
__device__ uint32_t g_Vh[N_NODES * 64];       // fp16 V, half2-packed
__device__ int      g_row_off[N_NODES + 1];
__device__ int      g_cnt[N_NODES];           // counts -> cursors; re-zeroed by aggregate
__device__ int      g_esrc[N_EDGES];          // src node id per CSR slot
__device__ int      g_part[SCAN_BLOCKS];

// bf16 split of h, packed 4 elems per uint2 (row-major halfword order)
__device__ uint2 g_hhi[N_NODES * 128 / 4];
__device__ uint2 g_hlo[N_NODES * 128 / 4];
// pre-swizzled weight fragments: [z][kstep][ntile][lane] -> {reg0, reg1} of mma B frag
__device__ uint2 g_wfhi[3][8][16][32];
__device__ uint2 g_wflo[3][8][16][32];

__device__ __forceinline__ uint32_t pack_bf2(__nv_bfloat16 a, __nv_bfloat16 b) {
    return (uint32_t)__bfloat16_as_ushort(a) | ((uint32_t)__bfloat16_as_ushort(b) << 16);
}

// ---------------- prep: z=0 split h, z=1 edge count (x4 ILP), z=2 weight fragments ----------------
__global__ void __launch_bounds__(256) prep_kernel(
    const float* __restrict__ h, const int* __restrict__ dst,
    const float* __restrict__ Wq, const float* __restrict__ Wk, const float* __restrict__ Wv)
{
    const int z = blockIdx.z;
    const int tid = blockIdx.x * 256 + threadIdx.x;

    if (z == 0) {
        // 6.4M floats / 4 per thread = 1.6M threads = 6250 blocks exactly
        float4 v = *reinterpret_cast<const float4*>(&h[tid * 4]);
        __nv_bfloat16 h0 = __float2bfloat16_rn(v.x);
        __nv_bfloat16 h1 = __float2bfloat16_rn(v.y);
        __nv_bfloat16 h2 = __float2bfloat16_rn(v.z);
        __nv_bfloat16 h3 = __float2bfloat16_rn(v.w);
        uint2 hi, lo;
        hi.x = pack_bf2(h0, h1);
        hi.y = pack_bf2(h2, h3);
        lo.x = pack_bf2(__float2bfloat16_rn(v.x - __bfloat162float(h0)),
                        __float2bfloat16_rn(v.y - __bfloat162float(h1)));
        lo.y = pack_bf2(__float2bfloat16_rn(v.z - __bfloat162float(h2)),
                        __float2bfloat16_rn(v.w - __bfloat162float(h3)));
        g_hhi[tid] = hi;
        g_hlo[tid] = lo;
    } else if (z == 1) {
        if (tid < N_EDGES / 4) {
            int4 d4 = reinterpret_cast<const int4*>(dst)[tid];
            atomicAdd(&g_cnt[d4.x], 1);
            atomicAdd(&g_cnt[d4.y], 1);
            atomicAdd(&g_cnt[d4.z], 1);
            atomicAdd(&g_cnt[d4.w], 1);
        }
    } else {
        // weight fragments: 3*8*16*32 = 12288 threads
        if (tid >= 3 * 8 * 16 * 32) return;
        int lane = tid & 31;
        int nt   = (tid >> 5) & 15;
        int ks   = (tid >> 9) & 7;
        int zz   = tid >> 12;
        const float* W = (zz == 0) ? Wq : (zz == 1) ? Wk : Wv;
        int g = lane >> 2, t = lane & 3;
        int n  = nt * 8 + g;
        int kb = ks * 16 + t * 2;
        float w0 = W[(kb + 0) * 128 + n];
        float w1 = W[(kb + 1) * 128 + n];
        float w2 = W[(kb + 8) * 128 + n];
        float w3 = W[(kb + 9) * 128 + n];
        __nv_bfloat16 b0 = __float2bfloat16_rn(w0);
        __nv_bfloat16 b1 = __float2bfloat16_rn(w1);
        __nv_bfloat16 b2 = __float2bfloat16_rn(w2);
        __nv_bfloat16 b3 = __float2bfloat16_rn(w3);
        uint2 hi, lo;
        hi.x = pack_bf2(b0, b1);
        hi.y = pack_bf2(b2, b3);
        lo.x = pack_bf2(__float2bfloat16_rn(w0 - __bfloat162float(b0)),
                        __float2bfloat16_rn(w1 - __bfloat162float(b1)));
        lo.y = pack_bf2(__float2bfloat16_rn(w2 - __bfloat162float(b2)),
                        __float2bfloat16_rn(w3 - __bfloat162float(b3)));
        g_wfhi[zz][ks][nt][lane] = hi;
        g_wflo[zz][ks][nt][lane] = lo;
    }
}

// ---------------- tensor-core GEMM: C[z] = h @ W[z] + b[z] via bf16-split ----------------
__device__ __forceinline__ void mma_bf16(float& c0, float& c1, float& c2, float& c3,
                                         uint32_t a0, uint32_t a1, uint32_t a2, uint32_t a3,
                                         uint32_t b0, uint32_t b1)
{
    asm volatile(
        "mma.sync.aligned.m16n8k16.row.col.f32.bf16.bf16.f32 "
        "{%0,%1,%2,%3},{%4,%5,%6,%7},{%8,%9},{%0,%1,%2,%3};"
        : "+f"(c0), "+f"(c1), "+f"(c2), "+f"(c3)
        : "r"(a0), "r"(a1), "r"(a2), "r"(a3), "r"(b0), "r"(b1));
}

// CTA = 16 m-rows x 128 n-cols x 3 weights. 4 warps; warp w owns n-tiles [4w, 4w+4).
// Epilogue: Q -> fp32, K/V -> packed half2.
__global__ void __launch_bounds__(128) gemm_mma(
    const float* __restrict__ bq, const float* __restrict__ bk, const float* __restrict__ bv)
{
    const int m0   = blockIdx.x * 16;
    const int w    = threadIdx.x >> 5;
    const int lane = threadIdx.x & 31;
    const int g    = lane >> 2;
    const int t    = lane & 3;

    float c[3][4][4];
    #pragma unroll
    for (int z = 0; z < 3; z++) {
        const float* bias = (z == 0) ? bq : (z == 1) ? bk : bv;
        #pragma unroll
        for (int nt = 0; nt < 4; nt++) {
            int col = (w * 4 + nt) * 8 + t * 2;
            float b0 = bias[col], b1 = bias[col + 1];
            c[z][nt][0] = b0; c[z][nt][1] = b1;
            c[z][nt][2] = b0; c[z][nt][3] = b1;
        }
    }

    const uint32_t* Ahi = reinterpret_cast<const uint32_t*>(g_hhi);
    const uint32_t* Alo = reinterpret_cast<const uint32_t*>(g_hlo);
    const int rowA = m0 + g;                 // 64 words per row

    #pragma unroll
    for (int pass = 0; pass < 3; pass++) {
        const uint32_t* A = (pass == 2) ? Alo : Ahi;
        const bool useLo = (pass == 1);
        #pragma unroll
        for (int ks = 0; ks < 8; ks++) {
            int kw = ks * 8 + t;
            uint32_t a0 = A[rowA * 64 + kw];
            uint32_t a1 = A[(rowA + 8) * 64 + kw];
            uint32_t a2 = A[rowA * 64 + kw + 4];
            uint32_t a3 = A[(rowA + 8) * 64 + kw + 4];
            #pragma unroll
            for (int z = 0; z < 3; z++) {
                #pragma unroll
                for (int nt = 0; nt < 4; nt++) {
                    uint2 b = useLo ? g_wflo[z][ks][w * 4 + nt][lane]
                                    : g_wfhi[z][ks][w * 4 + nt][lane];
                    mma_bf16(c[z][nt][0], c[z][nt][1], c[z][nt][2], c[z][nt][3],
                             a0, a1, a2, a3, b.x, b.y);
                }
            }
        }
    }

    #pragma unroll
    for (int nt = 0; nt < 4; nt++) {
        int col = (w * 4 + nt) * 8 + t * 2;
        // Q fp32
        *reinterpret_cast<float2*>(&g_Q[(m0 + g) * 128 + col])     = make_float2(c[0][nt][0], c[0][nt][1]);
        *reinterpret_cast<float2*>(&g_Q[(m0 + g + 8) * 128 + col]) = make_float2(c[0][nt][2], c[0][nt][3]);
        // K, V fp16 (half2 packed; col is even)
        __half2 klo = __floats2half2_rn(c[1][nt][0], c[1][nt][1]);
        __half2 khi = __floats2half2_rn(c[1][nt][2], c[1][nt][3]);
        __half2 vlo = __floats2half2_rn(c[2][nt][0], c[2][nt][1]);
        __half2 vhi = __floats2half2_rn(c[2][nt][2], c[2][nt][3]);
        g_Kh[(m0 + g) * 64 + col / 2]     = *reinterpret_cast<uint32_t*>(&klo);
        g_Kh[(m0 + g + 8) * 64 + col / 2] = *reinterpret_cast<uint32_t*>(&khi);
        g_Vh[(m0 + g) * 64 + col / 2]     = *reinterpret_cast<uint32_t*>(&vlo);
        g_Vh[(m0 + g + 8) * 64 + col / 2] = *reinterpret_cast<uint32_t*>(&vhi);
    }
}

// ---------------- parallel scan, stage 1 ----------------
__global__ void __launch_bounds__(256) scan_part_kernel()
{
    __shared__ int ws[8];
    int gid = blockIdx.x * 256 + threadIdx.x;
    int v = (gid < N_NODES) ? g_cnt[gid] : 0;
    int s = __reduce_add_sync(0xffffffffu, v);
    if ((threadIdx.x & 31) == 0) ws[threadIdx.x >> 5] = s;
    __syncthreads();
    if (threadIdx.x == 0) {
        int tot = 0;
        #pragma unroll
        for (int j = 0; j < 8; j++) tot += ws[j];
        g_part[blockIdx.x] = tot;
    }
}

// ---------------- parallel scan, stage 2 ----------------
__global__ void __launch_bounds__(256) scan_final_kernel()
{
    __shared__ int ps[8];
    __shared__ int ws[8];
    const int t = threadIdx.x, b = blockIdx.x;
    const int lane = t & 31, w = t >> 5;

    int pv = (t < b) ? g_part[t] : 0;
    int psum = __reduce_add_sync(0xffffffffu, pv);
    if (lane == 0) ps[w] = psum;
    __syncthreads();
    int offset = 0;
    #pragma unroll
    for (int j = 0; j < 8; j++) offset += ps[j];

    int gid = b * 256 + t;
    int c = (gid < N_NODES) ? g_cnt[gid] : 0;
    int incl = c;
    #pragma unroll
    for (int d = 1; d < 32; d <<= 1) {
        int u = __shfl_up_sync(0xffffffffu, incl, d);
        if (lane >= d) incl += u;
    }
    if (lane == 31) ws[w] = incl;
    __syncthreads();
    int woff = 0;
    #pragma unroll
    for (int j = 0; j < 8; j++) woff += (j < w) ? ws[j] : 0;

    int excl = offset + woff + incl - c;
    if (gid < N_NODES) {
        g_row_off[gid] = excl;
        g_cnt[gid]     = excl;           // cursor for scatter
    }
    if (gid == N_NODES - 1)
        g_row_off[N_NODES] = excl + c;
}

// ---------------- scatter: 4 edges/thread for atomic MLP ----------------
__global__ void __launch_bounds__(256) scatter_kernel(
    const int* __restrict__ src, const int* __restrict__ dst)
{
    int t = blockIdx.x * blockDim.x + threadIdx.x;
    if (t < N_EDGES / 4) {
        int4 d4 = reinterpret_cast<const int4*>(dst)[t];
        int4 s4 = reinterpret_cast<const int4*>(src)[t];
        int p0 = atomicAdd(&g_cnt[d4.x], 1);
        int p1 = atomicAdd(&g_cnt[d4.y], 1);
        int p2 = atomicAdd(&g_cnt[d4.z], 1);
        int p3 = atomicAdd(&g_cnt[d4.w], 1);
        g_esrc[p0] = s4.x;
        g_esrc[p1] = s4.y;
        g_esrc[p2] = s4.z;
        g_esrc[p3] = s4.w;
    }
}

// ---------------- aggregation: one warp per dst node, fp16 K/V ----------------
// lane l owns columns 4l..4l+3; each 4-lane quad owns one head (D=16).
__global__ void __launch_bounds__(256) aggregate_kernel(float* __restrict__ out)
{
    int warp = (blockIdx.x * blockDim.x + threadIdx.x) >> 5;
    int lane = threadIdx.x & 31;
    if (warp >= N_NODES) return;
    const int node = warp;

    const float4 q = *reinterpret_cast<const float4*>(&g_Q[node * 128 + lane * 4]);
    float4 acc = make_float4(0.f, 0.f, 0.f, 0.f);
    float  zz  = 0.f;

    const int beg = g_row_off[node];
    const int end = g_row_off[node + 1];
    for (int i = beg; i < end; ++i) {
        int s = g_esrc[i];
        uint2 kw = *reinterpret_cast<const uint2*>(&g_Kh[s * 64 + lane * 2]);
        float2 k01 = __half22float2(*reinterpret_cast<__half2*>(&kw.x));
        float2 k23 = __half22float2(*reinterpret_cast<__half2*>(&kw.y));
        float p = q.x * k01.x + q.y * k01.y + q.z * k23.x + q.w * k23.y;
        p += __shfl_xor_sync(0xffffffffu, p, 1);
        p += __shfl_xor_sync(0xffffffffu, p, 2);
        float sc = p * 0.25f;                       // 1/sqrt(16)
        sc = fminf(fmaxf(sc, -5.f), 5.f);
        float wgt = __expf(sc);
        uint2 vw = *reinterpret_cast<const uint2*>(&g_Vh[s * 64 + lane * 2]);
        float2 v01 = __half22float2(*reinterpret_cast<__half2*>(&vw.x));
        float2 v23 = __half22float2(*reinterpret_cast<__half2*>(&vw.y));
        acc.x += v01.x * wgt;
        acc.y += v01.y * wgt;
        acc.z += v23.x * wgt;
        acc.w += v23.y * wgt;
        zz += wgt;                                  // same across quad = z[head]
    }

    float inv = 1.f / (zz + 1e-6f);
    float4 o = make_float4(acc.x * inv, acc.y * inv, acc.z * inv, acc.w * inv);
    *reinterpret_cast<float4*>(&out[node * 128 + lane * 4]) = o;

    if (lane == 0) g_cnt[node] = 0;                 // restore invariant for next launch
}

// ---------------- launch ----------------
extern "C" void kernel_launch(void* const* d_in, const int* in_sizes, int n_in,
                              void* d_out, int out_size)
{
    const float* h   = (const float*)d_in[0];
    // d_in[1] (e), d_in[8] (We), d_in[9] (be) are unused by the reference output.
    const int*   src = (const int*)d_in[2];
    const int*   dst = (const int*)d_in[3];
    const float* Wq  = (const float*)d_in[4];
    const float* bq  = (const float*)d_in[5];
    const float* Wk  = (const float*)d_in[6];
    const float* bk  = (const float*)d_in[7];
    const float* Wv  = (const float*)d_in[10];
    const float* bv  = (const float*)d_in[11];
    float* out = (float*)d_out;

    dim3 prep_grid(6250, 1, 3);    // z=0: h split, z=1: edge count (x4), z=2: W frags
    prep_kernel<<<prep_grid, 256>>>(h, dst, Wq, Wk, Wv);

    scan_part_kernel<<<SCAN_BLOCKS, 256>>>();
    scan_final_kernel<<<SCAN_BLOCKS, 256>>>();
    scatter_kernel<<<E4_BLOCKS, 256>>>(src, dst);

    gemm_mma<<<M_TILES, 128>>>(bq, bk, bv);

    int agg_blocks = (N_NODES + 7) / 8;   // 8 warps (nodes) per 256-thread block
    aggregate_kernel<<<agg_blocks, 256>>>(out);
}